// round 1
// baseline (speedup 1.0000x reference)
#include <cuda_runtime.h>
#include <cuda_bf16.h>

#define NP 8192
#define TI 256            // i-particles per block (= threads per block)
#define TJ 512            // j-particles per block chunk
#define NSPLIT (NP / TJ)  // 16 j-chunks

#define INV_H 10.0f
#define H2    0.01f       // h^2
#define EPS   1e-10f

// 8 / (PI * H^3), computed in double then narrowed (matches reference constant)
__device__ __constant__ float kNorm = (float)(8.0 / (3.14159265 * 0.001));

__global__ void init_out_kernel(float* __restrict__ out) {
    int i = blockIdx.x * blockDim.x + threadIdx.x;
    if (i < NP) out[i] = 0.0f;
}

__global__ void __launch_bounds__(TI) sph_density_kernel(
    const float* __restrict__ pos, float* __restrict__ out)
{
    __shared__ float4 sj[TJ];

    const int i  = blockIdx.x * TI + threadIdx.x;
    const int j0 = blockIdx.y * TJ;

    // Cooperative load of this block's j-chunk into padded float4 smem.
    for (int t = threadIdx.x; t < TJ; t += TI) {
        const float* p = pos + 3 * (j0 + t);
        sj[t] = make_float4(p[0], p[1], p[2], 0.0f);
    }
    __syncthreads();

    const float xi = pos[3 * i + 0];
    const float yi = pos[3 * i + 1];
    const float zi = pos[3 * i + 2];

    float acc = 0.0f;

    #pragma unroll 2
    for (int t = 0; t < TJ; t += 4) {
        float r2[4];
        #pragma unroll
        for (int u = 0; u < 4; u++) {
            float4 p = sj[t + u];
            float dx = p.x - xi;
            float dy = p.y - yi;
            float dz = p.z - zi;
            r2[u] = fmaf(dx, dx, fmaf(dy, dy, fmaf(dz, dz, EPS)));
        }
        // Support test: q <= 1  <=>  r2 (incl. eps) <= h^2.
        float m = fminf(fminf(r2[0], r2[1]), fminf(r2[2], r2[3]));
        if (__any_sync(0xFFFFFFFFu, m <= H2)) {
            #pragma unroll
            for (int u = 0; u < 4; u++) {
                float r;
                asm("sqrt.approx.f32 %0, %1;" : "=f"(r) : "f"(r2[u]));
                float q   = r * INV_H;
                float qm1 = q - 1.0f;
                float wi  = fmaf(q * q * 6.0f, qm1, 1.0f);  // 1 - 6q^2 + 6q^3
                float t1  = qm1 * qm1;
                float wo  = -2.0f * t1 * qm1;               // 2(1-q)^3
                float w   = (q <= 0.5f) ? wi : wo;
                acc += (q <= 1.0f) ? w : 0.0f;
            }
        }
    }

    atomicAdd(&out[i], acc * kNorm);
}

extern "C" void kernel_launch(void* const* d_in, const int* in_sizes, int n_in,
                              void* d_out, int out_size)
{
    const float* pos = (const float*)d_in[0];
    float* out = (float*)d_out;
    (void)in_sizes; (void)n_in; (void)out_size;

    init_out_kernel<<<(NP + 255) / 256, 256>>>(out);
    sph_density_kernel<<<dim3(NP / TI, NSPLIT), TI>>>(pos, out);
}